// round 11
// baseline (speedup 1.0000x reference)
#include <cuda_runtime.h>
#include <math.h>

typedef unsigned long long u64;

__device__ __forceinline__ u64 pk2(float lo, float hi) {
    u64 r; asm("mov.b64 %0, {%1,%2};" : "=l"(r) : "f"(lo), "f"(hi)); return r;
}
__device__ __forceinline__ float2 up2(u64 v) {
    float2 r; asm("mov.b64 {%0,%1}, %2;" : "=f"(r.x), "=f"(r.y) : "l"(v)); return r;
}
__device__ __forceinline__ void fma2(u64& d, u64 a, u64 b) {
    asm("fma.rn.f32x2 %0, %1, %2, %3;" : "=l"(d) : "l"(a), "l"(b), "l"(d));
}
__device__ __forceinline__ u64 add2(u64 a, u64 b) {
    u64 r; asm("add.rn.f32x2 %0, %1, %2;" : "=l"(r) : "l"(a), "l"(b)); return r;
}
__device__ __forceinline__ u64 sub2(u64 a, u64 b) {
    float2 x = up2(a), y = up2(b); return pk2(x.x - y.x, x.y - y.y);
}
__device__ __forceinline__ float hadd(u64 v) { float2 t = up2(v); return t.x + t.y; }

__device__ float g_Yx [1024*2048];      // [img][l][h]  stage-1 output
__device__ float g_Yy [1024*2048];
__device__ float g_Xx [256*1024];
__device__ float g_Xy [256*1024];
__device__ float g_Wtx[256*4096];
__device__ float g_Wty[256*4096];
__device__ float g_OFx[1024*256];
__device__ float g_OFy[1024*256];
__device__ float g_Ax [16*128*64*16];   // [b][h][o][l], scaled, 2x folded
__device__ float g_Ay [16*128*64*16];
__device__ float g_bwT[4096];           // [i][o]
__device__ float g_proj[1024];

__global__ void k_proj(const float* __restrict__ t_emb, const float* __restrict__ temb_w,
                       const float* __restrict__ temb_b) {
    int bo = blockIdx.x, b = bo >> 6, o = bo & 63, tid = threadIdx.x;
    const float* te = t_emb + b * 512;
    const float* tw = temb_w + o * 512;
    float part = 0.f;
    for (int c = tid; c < 512; c += 128) {
        float v = te[c];
        part += (v / (1.f + expf(-v))) * tw[c];
    }
    for (int off = 16; off; off >>= 1) part += __shfl_down_sync(~0u, part, off);
    __shared__ float ws[4];
    if ((tid & 31) == 0) ws[tid >> 5] = part;
    __syncthreads();
    if (tid == 0) g_proj[bo] = ws[0] + ws[1] + ws[2] + ws[3] + temb_b[o];
}

// weights [i][o][kl] -> SoA [kl][o*64+i]
__global__ void k_wt(const float* __restrict__ wr, const float* __restrict__ wi) {
    __shared__ float tr[32][33], ti[32][33];
    int kl0 = blockIdx.x * 32, io0 = blockIdx.y * 32;
    int tx = threadIdx.x, ty = threadIdx.y;
    #pragma unroll
    for (int j = 0; j < 32; j += 8) {
        int io = io0 + ty + j;
        tr[ty + j][tx] = wr[io * 256 + kl0 + tx];
        ti[ty + j][tx] = wi[io * 256 + kl0 + tx];
    }
    __syncthreads();
    #pragma unroll
    for (int j = 0; j < 32; j += 8) {
        int kl = kl0 + ty + j, io = io0 + tx;
        int i = io >> 6, o = io & 63;
        g_Wtx[kl * 4096 + o * 64 + i] = tr[tx][ty + j];
        g_Wty[kl * 4096 + o * 64 + i] = ti[tx][ty + j];
    }
}

__global__ void k_bwt(const float* __restrict__ bypw) {
    int t = blockIdx.x * 256 + threadIdx.x;
    int i = t >> 6, o = t & 63;
    g_bwT[i * 64 + o] = bypw[o * 64 + i];
}

// stage 1 per half-image (64 rows): fold + Y[l][h], high occupancy
__global__ void __launch_bounds__(256, 3) k_fwd1(const float* __restrict__ x) {
    extern __shared__ char sm[];
    float* xs  = (float*)sm;                // 64 x 132          33792 B
    u64*   tc  = (u64*)(sm + 33792);        // 16 x 34 u64        4352 B
    u64*   ts  = (u64*)(sm + 38144);        //                    4352 B
    float* Ysx = (float*)(sm + 42496);      // 16 x 68            4352 B
    float* Ysy = (float*)(sm + 46848);      //                    4352 B -> 51200
    int tid = threadIdx.x;
    int img = blockIdx.x >> 1, half = blockIdx.x & 1;
    const float* xb = x + (size_t)img * 16384 + half * 8192;

    #pragma unroll
    for (int j = 0; j < 8; j++) {
        int idx4 = tid + j * 256;            // 2048 float4 = 64 rows x 32
        int row = idx4 >> 5, wq = idx4 & 31;
        *(float4*)(xs + row * 132 + wq * 4) = ((const float4*)xb)[idx4];
    }
    for (int e = tid; e < 512; e += 256) {
        int m = e >> 5, p = e & 31;
        float s0, c0, s1, c1;
        sincospif((float)(m * (2 * p))     * (1.f / 64.f), &s0, &c0);
        sincospif((float)(m * (2 * p + 1)) * (1.f / 64.f), &s1, &c1);
        tc[m * 34 + p] = pk2(c0, c1);
        ts[m * 34 + p] = pk2(-s0, -s1);
    }
    __syncthreads();

    // radix-2 fold in place: [w]=x+x', [64+w]=x-x'
    #pragma unroll
    for (int j = 0; j < 4; j++) {
        int idx = tid + j * 256;             // 1024 = 64 rows x 16 quads
        int h = idx >> 4, q = idx & 15;
        float4* pe = (float4*)(xs + h * 132 + q * 4);
        float4* po = (float4*)(xs + h * 132 + 64 + q * 4);
        float4 a = *pe, bq = *po;
        *pe = make_float4(a.x + bq.x, a.y + bq.y, a.z + bq.z, a.w + bq.w);
        *po = make_float4(a.x - bq.x, a.y - bq.y, a.z - bq.z, a.w - bq.w);
    }
    __syncthreads();

    {   // stage 1: thread = (h_low, l-pair); rows h_low, h_low+32
        int h_low = tid >> 3;
        int lp = tid & 7, le = 2 * lp, lo = le + 1;
        u64 aR[2][2], aI[2][2];
        aR[0][0]=aR[0][1]=aR[1][0]=aR[1][1]=0ull;
        aI[0][0]=aI[0][1]=aI[1][0]=aI[1][1]=0ull;
        #pragma unroll 4
        for (int w = 0; w < 64; w += 4) {
            int wp = w >> 1;
            ulonglong2 e0 = *(ulonglong2*)(xs + h_low*132 + w);
            ulonglong2 e1 = *(ulonglong2*)(xs + (h_low+32)*132 + w);
            ulonglong2 q0 = *(ulonglong2*)(xs + h_low*132 + 64 + w);
            ulonglong2 q1 = *(ulonglong2*)(xs + (h_low+32)*132 + 64 + w);
            u64 ce0 = tc[le*34+wp], ce1 = tc[le*34+wp+1];
            u64 se0 = ts[le*34+wp], se1 = ts[le*34+wp+1];
            u64 co0 = tc[lo*34+wp], co1 = tc[lo*34+wp+1];
            u64 so0 = ts[lo*34+wp], so1 = ts[lo*34+wp+1];
            fma2(aR[0][0], e0.x, ce0); fma2(aR[0][0], e0.y, ce1);
            fma2(aI[0][0], e0.x, se0); fma2(aI[0][0], e0.y, se1);
            fma2(aR[1][0], e1.x, ce0); fma2(aR[1][0], e1.y, ce1);
            fma2(aI[1][0], e1.x, se0); fma2(aI[1][0], e1.y, se1);
            fma2(aR[0][1], q0.x, co0); fma2(aR[0][1], q0.y, co1);
            fma2(aI[0][1], q0.x, so0); fma2(aI[0][1], q0.y, so1);
            fma2(aR[1][1], q1.x, co0); fma2(aR[1][1], q1.y, co1);
            fma2(aI[1][1], q1.x, so0); fma2(aI[1][1], q1.y, so1);
        }
        Ysx[le*68 + h_low]      = hadd(aR[0][0]);
        Ysx[lo*68 + h_low]      = hadd(aR[0][1]);
        Ysx[le*68 + h_low + 32] = hadd(aR[1][0]);
        Ysx[lo*68 + h_low + 32] = hadd(aR[1][1]);
        Ysy[le*68 + h_low]      = hadd(aI[0][0]);
        Ysy[lo*68 + h_low]      = hadd(aI[0][1]);
        Ysy[le*68 + h_low + 32] = hadd(aI[1][0]);
        Ysy[lo*68 + h_low + 32] = hadd(aI[1][1]);
    }
    __syncthreads();

    float* gx = g_Yx + (size_t)img * 2048 + half * 64;
    float* gy = g_Yy + (size_t)img * 2048 + half * 64;
    #pragma unroll
    for (int j = 0; j < 4; j++) {
        int idx = tid + j * 256;             // 1024 = 16 l x 64 h
        int l = idx >> 6, hh = idx & 63;
        gx[l * 128 + hh] = Ysx[l * 68 + hh];
        gy[l * 128 + hh] = Ysy[l * 68 + hh];
    }
}

// stage 2 per image: X[k][l] = (1/128) sum_h e^{-i k h th} Y[h][l]
__global__ void __launch_bounds__(256) k_fwd2() {
    __shared__ float Ysx[16*130], Ysy[16*130];
    __shared__ u64 tc[16*65], ts[16*65];
    int tid = threadIdx.x, img = blockIdx.x;
    for (int e = tid; e < 1024; e += 256) {
        int m = e >> 6, p = e & 63;
        float s0, c0, s1, c1;
        sincospif((float)(m * (2 * p))     * (1.f / 64.f), &s0, &c0);
        sincospif((float)(m * (2 * p + 1)) * (1.f / 64.f), &s1, &c1);
        tc[m * 65 + p] = pk2(c0, c1);
        ts[m * 65 + p] = pk2(-s0, -s1);
    }
    const float* gx = g_Yx + (size_t)img * 2048;
    const float* gy = g_Yy + (size_t)img * 2048;
    #pragma unroll
    for (int j = 0; j < 8; j++) {
        int idx = tid + j * 256;             // 2048 = 16 l x 128 h
        int l = idx >> 7, hh = idx & 127;
        Ysx[l * 130 + hh] = gx[idx];
        Ysy[l * 130 + hh] = gy[idx];
    }
    __syncthreads();

    int k = tid >> 4, l = tid & 15;
    u64 aA=0ull, aB=0ull, aC=0ull, aD=0ull;
    #pragma unroll 8
    for (int hp = 0; hp < 64; hp++) {
        u64 tck = tc[k*65+hp], tsk = ts[k*65+hp];
        u64 Yxp = *(u64*)(Ysx + l*130 + 2*hp);
        u64 Yyp = *(u64*)(Ysy + l*130 + 2*hp);
        fma2(aA, tck, Yxp); fma2(aB, tsk, Yyp);
        fma2(aC, tck, Yyp); fma2(aD, tsk, Yxp);
    }
    g_Xx[tid*1024 + img] = (hadd(aA) - hadd(aB)) * 0.0078125f;
    g_Xy[tid*1024 + img] = (hadd(aC) + hadd(aD)) * 0.0078125f;
}

// spectral mix per mode kl
__global__ void __launch_bounds__(256) k_spec() {
    __shared__ float Xxs[1024], Xys[1024];
    __shared__ float Wxs[64*66], Wys[64*66];
    int kl = blockIdx.x, tid = threadIdx.x;
    for (int j = tid; j < 1024; j += 256) { Xxs[j] = g_Xx[kl*1024+j]; Xys[j] = g_Xy[kl*1024+j]; }
    for (int j = tid; j < 4096; j += 256) {
        int o = j >> 6, i = j & 63;
        Wxs[o*66+i] = g_Wtx[kl*4096+j];
        Wys[o*66+i] = g_Wty[kl*4096+j];
    }
    __syncthreads();
    int b = tid >> 4, o0 = tid & 15;
    u64 aA[4], aB[4], aC[4], aD[4];
    #pragma unroll
    for (int j = 0; j < 4; j++) { aA[j]=aB[j]=aC[j]=aD[j]=0ull; }
    #pragma unroll 4
    for (int ip = 0; ip < 32; ip++) {
        u64 Xxp = *(u64*)(Xxs + b*64 + 2*ip);
        u64 Xyp = *(u64*)(Xys + b*64 + 2*ip);
        #pragma unroll
        for (int j = 0; j < 4; j++) {
            int o = o0 + 16*j;
            u64 Wxp = *(u64*)(Wxs + o*66 + 2*ip);
            u64 Wyp = *(u64*)(Wys + o*66 + 2*ip);
            fma2(aA[j], Xxp, Wxp); fma2(aB[j], Xyp, Wyp);
            fma2(aC[j], Xxp, Wyp); fma2(aD[j], Xyp, Wxp);
        }
    }
    #pragma unroll
    for (int j = 0; j < 4; j++) {
        int bo = b*64 + o0 + 16*j;
        g_OFx[bo*256 + kl] = hadd(aA[j]) - hadd(aB[j]);
        g_OFy[bo*256 + kl] = hadd(aC[j]) + hadd(aD[j]);
    }
}

// inverse along h per (b,o)
__global__ void __launch_bounds__(256) k_invA() {
    __shared__ u64 tcT[128*9], tsT[128*9];
    __shared__ float Fxs[16*18], Fys[16*18];
    int tid = threadIdx.x, bo = blockIdx.x;
    for (int e = tid; e < 1024; e += 256) {
        int h = e >> 3, kp = e & 7;
        float s0, c0, s1, c1;
        sincospif((float)(h * (2*kp))   * (1.f/64.f), &s0, &c0);
        sincospif((float)(h * (2*kp+1)) * (1.f/64.f), &s1, &c1);
        tcT[h*9+kp] = pk2(c0, c1);
        tsT[h*9+kp] = pk2(-s0, -s1);
    }
    {
        int k = tid >> 4, l = tid & 15;
        Fxs[l*18+k] = g_OFx[bo*256 + tid];
        Fys[l*18+k] = g_OFy[bo*256 + tid];
    }
    __syncthreads();
    int h = tid >> 1, l0 = (tid & 1) * 8;
    u64 aA[8], aB[8], aC[8], aD[8];
    #pragma unroll
    for (int j = 0; j < 8; j++) { aA[j]=aB[j]=aC[j]=aD[j]=0ull; }
    #pragma unroll
    for (int kp = 0; kp < 8; kp++) {
        u64 tck = tcT[h*9+kp], tsk = tsT[h*9+kp];
        #pragma unroll
        for (int j = 0; j < 8; j++) {
            u64 Fxp = *(u64*)(Fxs + (l0+j)*18 + 2*kp);
            u64 Fyp = *(u64*)(Fys + (l0+j)*18 + 2*kp);
            fma2(aA[j], tck, Fxp); fma2(aB[j], tsk, Fyp);
            fma2(aC[j], tck, Fyp); fma2(aD[j], tsk, Fxp);
        }
    }
    int b = bo >> 6, o = bo & 63;
    float* ox = g_Ax + ((size_t)(b*128 + h)*64 + o)*16 + l0;
    float* oy = g_Ay + ((size_t)(b*128 + h)*64 + o)*16 + l0;
    float rx[8], ry[8];
    #pragma unroll
    for (int j = 0; j < 8; j++) {
        float sc = (l0 + j == 0) ? 0.0078125f : 0.015625f;
        rx[j] = (hadd(aA[j]) + hadd(aB[j])) * sc;
        ry[j] = (hadd(aC[j]) - hadd(aD[j])) * sc;
    }
    *(float4*)(ox)   = make_float4(rx[0],rx[1],rx[2],rx[3]);
    *(float4*)(ox+4) = make_float4(rx[4],rx[5],rx[6],rx[7]);
    *(float4*)(oy)   = make_float4(ry[0],ry[1],ry[2],ry[3]);
    *(float4*)(oy+4) = make_float4(ry[4],ry[5],ry[6],ry[7]);
}

// final fused per (b,h): irfft E/O fold + bypass GEMM + GeLU + temb
__global__ void __launch_bounds__(256, 3) k_final(const float* __restrict__ x,
                                                  const float* __restrict__ bypb,
                                                  float* __restrict__ out) {
    extern __shared__ char sm[];
    float* xs  = (float*)sm;            // 64 x 132            33792 B
    float* bw  = (float*)(sm + 33792);  // [i][o]              16384 B
    float* Axs = (float*)(sm + 50176);  //                      4096 B
    float* Ays = (float*)(sm + 54272);  //                      4096 B
    u64*   tcw = (u64*)(sm + 58368);    // [l][wp<32] s34       4352 B
    u64*   tsw = (u64*)(sm + 62720);    //                      4352 B
    float* pb  = (float*)(sm + 67072);
    float* pj  = (float*)(sm + 67328);  // -> 67584

    int tid = threadIdx.x;
    int b = blockIdx.x >> 7, h = blockIdx.x & 127;
    const float* xbase = x + (size_t)b * 64 * 16384 + h * 128;

    #pragma unroll
    for (int j = 0; j < 8; j++) {
        int idx4 = tid + j * 256;
        int i = idx4 >> 5, wq = idx4 & 31;
        *(float4*)(xs + i*132 + wq*4) = *(const float4*)(xbase + i*16384 + wq*4);
    }
    #pragma unroll
    for (int j = 0; j < 4; j++)
        ((float4*)bw)[tid + j*256] = ((const float4*)g_bwT)[tid + j*256];
    {
        const float* Abx = g_Ax + (size_t)(b*128 + h) * 1024;
        const float* Aby = g_Ay + (size_t)(b*128 + h) * 1024;
        *(float4*)(Axs + tid*4) = *(const float4*)(Abx + tid*4);
        *(float4*)(Ays + tid*4) = *(const float4*)(Aby + tid*4);
    }
    for (int e = tid; e < 512; e += 256) {
        int l = e >> 5, wp = e & 31;
        float s0, c0, s1, c1;
        sincospif((float)(l * (2*wp))   * (1.f/64.f), &s0, &c0);
        sincospif((float)(l * (2*wp+1)) * (1.f/64.f), &s1, &c1);
        tcw[l*34+wp] = pk2(c0, c1);
        tsw[l*34+wp] = pk2(-s0, -s1);
    }
    if (tid < 64) { pb[tid] = bypb[tid]; pj[tid] = g_proj[b*64 + tid]; }
    __syncthreads();

    int o0 = (tid >> 4) * 4, wL = tid & 15;
    int wA = wL * 4, wB = 64 + wL * 4;

    u64 acc[4][4];
    {
        u64 E[4][2], O[4][2];
        #pragma unroll
        for (int j = 0; j < 4; j++) { E[j][0]=E[j][1]=O[j][0]=O[j][1]=0ull; }
        #pragma unroll 4
        for (int l = 0; l < 16; l++) {
            ulonglong2 cA = *(ulonglong2*)(tcw + l*34 + 2*wL);
            ulonglong2 sA = *(ulonglong2*)(tsw + l*34 + 2*wL);
            #pragma unroll
            for (int j = 0; j < 4; j++) {
                u64 ax = pk2(Axs[(o0+j)*16 + l], Axs[(o0+j)*16 + l]);
                u64 ay = pk2(Ays[(o0+j)*16 + l], Ays[(o0+j)*16 + l]);
                if ((l & 1) == 0) {
                    fma2(E[j][0], ax, cA.x); fma2(E[j][0], ay, sA.x);
                    fma2(E[j][1], ax, cA.y); fma2(E[j][1], ay, sA.y);
                } else {
                    fma2(O[j][0], ax, cA.x); fma2(O[j][0], ay, sA.x);
                    fma2(O[j][1], ax, cA.y); fma2(O[j][1], ay, sA.y);
                }
            }
        }
        #pragma unroll
        for (int j = 0; j < 4; j++) {
            acc[j][0] = add2(E[j][0], O[j][0]);
            acc[j][1] = add2(E[j][1], O[j][1]);
            acc[j][2] = sub2(E[j][0], O[j][0]);
            acc[j][3] = sub2(E[j][1], O[j][1]);
        }
    }

    #pragma unroll 4
    for (int i = 0; i < 64; i++) {
        ulonglong2 xa = *(ulonglong2*)(xs + i*132 + wA);
        ulonglong2 xc = *(ulonglong2*)(xs + i*132 + wB);
        float2 b01f = *(float2*)(bw + i*64 + o0);
        float2 b23f = *(float2*)(bw + i*64 + o0 + 2);
        u64 b0 = pk2(b01f.x, b01f.x), b1 = pk2(b01f.y, b01f.y);
        u64 b2 = pk2(b23f.x, b23f.x), b3 = pk2(b23f.y, b23f.y);
        fma2(acc[0][0], b0, xa.x); fma2(acc[0][1], b0, xa.y);
        fma2(acc[0][2], b0, xc.x); fma2(acc[0][3], b0, xc.y);
        fma2(acc[1][0], b1, xa.x); fma2(acc[1][1], b1, xa.y);
        fma2(acc[1][2], b1, xc.x); fma2(acc[1][3], b1, xc.y);
        fma2(acc[2][0], b2, xa.x); fma2(acc[2][1], b2, xa.y);
        fma2(acc[2][2], b2, xc.x); fma2(acc[2][3], b2, xc.y);
        fma2(acc[3][0], b3, xa.x); fma2(acc[3][1], b3, xa.y);
        fma2(acc[3][2], b3, xc.x); fma2(acc[3][3], b3, xc.y);
    }

    float* obase = out + (size_t)b * 64 * 16384 + h * 128;
    const float is2 = 0.70710678118654752f;
    #pragma unroll
    for (int j = 0; j < 4; j++) {
        int o = o0 + j;
        float bias = pb[o], pr = pj[o];
        float g[8];
        #pragma unroll
        for (int p = 0; p < 4; p++) {
            float2 t = up2(acc[j][p]);
            float v0 = t.x + bias, v1 = t.y + bias;
            g[2*p]   = 0.5f * v0 * (1.f + erff(v0 * is2)) + pr;
            g[2*p+1] = 0.5f * v1 * (1.f + erff(v1 * is2)) + pr;
        }
        *(float4*)(obase + o*16384 + wA) = make_float4(g[0],g[1],g[2],g[3]);
        *(float4*)(obase + o*16384 + wB) = make_float4(g[4],g[5],g[6],g[7]);
    }
}

extern "C" void kernel_launch(void* const* d_in, const int* in_sizes, int n_in,
                              void* d_out, int out_size) {
    const float* x     = (const float*)d_in[0];
    const float* t_emb = (const float*)d_in[1];
    const float* wr    = (const float*)d_in[2];
    const float* wi    = (const float*)d_in[3];
    const float* bypw  = (const float*)d_in[4];
    const float* bypb  = (const float*)d_in[5];
    const float* tw    = (const float*)d_in[6];
    const float* tb    = (const float*)d_in[7];
    float* out = (float*)d_out;

    cudaFuncSetAttribute(k_fwd1,  cudaFuncAttributeMaxDynamicSharedMemorySize, 51200);
    cudaFuncSetAttribute(k_final, cudaFuncAttributeMaxDynamicSharedMemorySize, 67584);

    k_proj<<<1024, 128>>>(t_emb, tw, tb);
    k_wt  <<<dim3(8, 128), dim3(32, 8)>>>(wr, wi);
    k_bwt <<<16, 256>>>(bypw);
    k_fwd1<<<2048, 256, 51200>>>(x);
    k_fwd2<<<1024, 256>>>();
    k_spec<<<256, 256>>>();
    k_invA<<<1024, 256>>>();
    k_final<<<2048, 256, 67584>>>(x, bypb, out);
}

// round 17
// speedup vs baseline: 1.0909x; 1.0909x over previous
#include <cuda_runtime.h>
#include <math.h>

typedef unsigned long long u64;

__device__ __forceinline__ u64 pk2(float lo, float hi) {
    u64 r; asm("mov.b64 %0, {%1,%2};" : "=l"(r) : "f"(lo), "f"(hi)); return r;
}
__device__ __forceinline__ float2 up2(u64 v) {
    float2 r; asm("mov.b64 {%0,%1}, %2;" : "=f"(r.x), "=f"(r.y) : "l"(v)); return r;
}
__device__ __forceinline__ void fma2(u64& d, u64 a, u64 b) {
    asm("fma.rn.f32x2 %0, %1, %2, %3;" : "=l"(d) : "l"(a), "l"(b), "l"(d));
}
__device__ __forceinline__ u64 add2(u64 a, u64 b) {
    u64 r; asm("add.rn.f32x2 %0, %1, %2;" : "=l"(r) : "l"(a), "l"(b)); return r;
}
__device__ __forceinline__ u64 sub2(u64 a, u64 b) {
    float2 x = up2(a), y = up2(b); return pk2(x.x - y.x, x.y - y.y);
}
__device__ __forceinline__ float hadd(u64 v) { float2 t = up2(v); return t.x + t.y; }

__device__ float g_Xx [256*1024];
__device__ float g_Xy [256*1024];
__device__ float g_Wtx[256*4096];
__device__ float g_Wty[256*4096];
__device__ float g_OFx[1024*256];
__device__ float g_OFy[1024*256];
__device__ float g_Ax [16*128*64*16];   // [b][h][o][l], scaled, 2x folded
__device__ float g_Ay [16*128*64*16];
__device__ float g_bwT[4096];           // [i][o]
__device__ float g_proj[1024];

__global__ void k_proj(const float* __restrict__ t_emb, const float* __restrict__ temb_w,
                       const float* __restrict__ temb_b) {
    int bo = blockIdx.x, b = bo >> 6, o = bo & 63, tid = threadIdx.x;
    const float* te = t_emb + b * 512;
    const float* tw = temb_w + o * 512;
    float part = 0.f;
    for (int c = tid; c < 512; c += 128) {
        float v = te[c];
        part += (v / (1.f + expf(-v))) * tw[c];
    }
    for (int off = 16; off; off >>= 1) part += __shfl_down_sync(~0u, part, off);
    __shared__ float ws[4];
    if ((tid & 31) == 0) ws[tid >> 5] = part;
    __syncthreads();
    if (tid == 0) g_proj[bo] = ws[0] + ws[1] + ws[2] + ws[3] + temb_b[o];
}

// weights [i][o][kl] -> SoA [kl][o*64+i]
__global__ void k_wt(const float* __restrict__ wr, const float* __restrict__ wi) {
    __shared__ float tr[32][33], ti[32][33];
    int kl0 = blockIdx.x * 32, io0 = blockIdx.y * 32;
    int tx = threadIdx.x, ty = threadIdx.y;
    #pragma unroll
    for (int j = 0; j < 32; j += 8) {
        int io = io0 + ty + j;
        tr[ty + j][tx] = wr[io * 256 + kl0 + tx];
        ti[ty + j][tx] = wi[io * 256 + kl0 + tx];
    }
    __syncthreads();
    #pragma unroll
    for (int j = 0; j < 32; j += 8) {
        int kl = kl0 + ty + j, io = io0 + tx;
        int i = io >> 6, o = io & 63;
        g_Wtx[kl * 4096 + o * 64 + i] = tr[tx][ty + j];
        g_Wty[kl * 4096 + o * 64 + i] = ti[tx][ty + j];
    }
}

__global__ void k_bwt(const float* __restrict__ bypw) {
    int t = blockIdx.x * 256 + threadIdx.x;
    int i = t >> 6, o = t & 63;
    g_bwT[i * 64 + o] = bypw[o * 64 + i];
}

// forward truncated DFT per (b,i), radix-2 fold; combined 16B twiddle entries
__global__ void __launch_bounds__(256, 2) k_fwd(const float* __restrict__ x) {
    extern __shared__ char sm[];
    float*      xs  = (float*)sm;                 // 128 x 132     67584 B
    ulonglong2* tbl = (ulonglong2*)(sm + 67584);  // [16][65] 16B  16640 B
    float*      Ysx = (float*)(sm + 84224);       // [l][h] s130    8320 B
    float*      Ysy = (float*)(sm + 92544);       //                8320 B -> 100864
    int tid = threadIdx.x;
    const float* xb = x + (size_t)blockIdx.x * 16384;

    #pragma unroll
    for (int j = 0; j < 16; j++) {
        int idx4 = tid + j * 256;
        int row = idx4 >> 5, wq = idx4 & 31;
        *(float4*)(xs + row * 132 + wq * 4) = ((const float4*)xb)[idx4];
    }
    for (int e = tid; e < 1024; e += 256) {
        int m = e >> 6, p = e & 63;
        float s0, c0, s1, c1;
        sincospif((float)(m * (2 * p))     * (1.f / 64.f), &s0, &c0);
        sincospif((float)(m * (2 * p + 1)) * (1.f / 64.f), &s1, &c1);
        ulonglong2 ent;
        ent.x = pk2(c0, c1);
        ent.y = pk2(-s0, -s1);
        tbl[m * 65 + p] = ent;
    }
    __syncthreads();

    // radix-2 fold in place: [w]=x+x', [64+w]=x-x'
    #pragma unroll
    for (int j = 0; j < 8; j++) {
        int idx = tid + j * 256;             // 2048 = 128 rows x 16 quads
        int h = idx >> 4, q = idx & 15;
        float4* pe = (float4*)(xs + h * 132 + q * 4);
        float4* po = (float4*)(xs + h * 132 + 64 + q * 4);
        float4 a = *pe, bq = *po;
        *pe = make_float4(a.x + bq.x, a.y + bq.y, a.z + bq.z, a.w + bq.w);
        *po = make_float4(a.x - bq.x, a.y - bq.y, a.z - bq.z, a.w - bq.w);
    }
    __syncthreads();

    { // stage 1: Y[l][h]; even l uses xe, odd l uses xo, 64 w's each
        int h_low = tid >> 3;
        int lp = tid & 7, le = 2 * lp, lo = le + 1;
        u64 aR[4][2], aI[4][2];
        #pragma unroll
        for (int r = 0; r < 4; r++) { aR[r][0]=aR[r][1]=aI[r][0]=aI[r][1]=0ull; }
        #pragma unroll 2
        for (int w = 0; w < 64; w += 4) {
            int wp = w >> 1;
            ulonglong2 e0 = *(ulonglong2*)(xs + (h_low +  0)*132 + w);
            ulonglong2 e1 = *(ulonglong2*)(xs + (h_low + 32)*132 + w);
            ulonglong2 e2 = *(ulonglong2*)(xs + (h_low + 64)*132 + w);
            ulonglong2 e3 = *(ulonglong2*)(xs + (h_low + 96)*132 + w);
            ulonglong2 o0 = *(ulonglong2*)(xs + (h_low +  0)*132 + 64 + w);
            ulonglong2 o1 = *(ulonglong2*)(xs + (h_low + 32)*132 + 64 + w);
            ulonglong2 o2 = *(ulonglong2*)(xs + (h_low + 64)*132 + 64 + w);
            ulonglong2 o3 = *(ulonglong2*)(xs + (h_low + 96)*132 + 64 + w);
            ulonglong2 te0 = tbl[le * 65 + wp];
            ulonglong2 te1 = tbl[le * 65 + wp + 1];
            ulonglong2 to0 = tbl[lo * 65 + wp];
            ulonglong2 to1 = tbl[lo * 65 + wp + 1];
            fma2(aR[0][0], e0.x, te0.x); fma2(aR[0][0], e0.y, te1.x);
            fma2(aI[0][0], e0.x, te0.y); fma2(aI[0][0], e0.y, te1.y);
            fma2(aR[1][0], e1.x, te0.x); fma2(aR[1][0], e1.y, te1.x);
            fma2(aI[1][0], e1.x, te0.y); fma2(aI[1][0], e1.y, te1.y);
            fma2(aR[2][0], e2.x, te0.x); fma2(aR[2][0], e2.y, te1.x);
            fma2(aI[2][0], e2.x, te0.y); fma2(aI[2][0], e2.y, te1.y);
            fma2(aR[3][0], e3.x, te0.x); fma2(aR[3][0], e3.y, te1.x);
            fma2(aI[3][0], e3.x, te0.y); fma2(aI[3][0], e3.y, te1.y);
            fma2(aR[0][1], o0.x, to0.x); fma2(aR[0][1], o0.y, to1.x);
            fma2(aI[0][1], o0.x, to0.y); fma2(aI[0][1], o0.y, to1.y);
            fma2(aR[1][1], o1.x, to0.x); fma2(aR[1][1], o1.y, to1.x);
            fma2(aI[1][1], o1.x, to0.y); fma2(aI[1][1], o1.y, to1.y);
            fma2(aR[2][1], o2.x, to0.x); fma2(aR[2][1], o2.y, to1.x);
            fma2(aI[2][1], o2.x, to0.y); fma2(aI[2][1], o2.y, to1.y);
            fma2(aR[3][1], o3.x, to0.x); fma2(aR[3][1], o3.y, to1.x);
            fma2(aI[3][1], o3.x, to0.y); fma2(aI[3][1], o3.y, to1.y);
        }
        #pragma unroll
        for (int r = 0; r < 4; r++) {
            Ysx[le*130 + h_low + 32*r] = hadd(aR[r][0]);
            Ysx[lo*130 + h_low + 32*r] = hadd(aR[r][1]);
            Ysy[le*130 + h_low + 32*r] = hadd(aI[r][0]);
            Ysy[lo*130 + h_low + 32*r] = hadd(aI[r][1]);
        }
    }
    __syncthreads();

    { // stage 2: X[k][l] = (1/128) sum_h e^{-i k h th} Y[h][l]
        int k = tid >> 4, l = tid & 15;
        u64 aA=0ull, aB=0ull, aC=0ull, aD=0ull;
        #pragma unroll 8
        for (int hp = 0; hp < 64; hp++) {
            ulonglong2 t = tbl[k * 65 + hp];
            u64 Yxp = *(u64*)(Ysx + l*130 + 2*hp);
            u64 Yyp = *(u64*)(Ysy + l*130 + 2*hp);
            fma2(aA, t.x, Yxp); fma2(aB, t.y, Yyp);
            fma2(aC, t.x, Yyp); fma2(aD, t.y, Yxp);
        }
        g_Xx[tid*1024 + blockIdx.x] = (hadd(aA) - hadd(aB)) * 0.0078125f;
        g_Xy[tid*1024 + blockIdx.x] = (hadd(aC) + hadd(aD)) * 0.0078125f;
    }
}

// spectral mix per mode kl
__global__ void __launch_bounds__(256) k_spec() {
    __shared__ float Xxs[1024], Xys[1024];
    __shared__ float Wxs[64*66], Wys[64*66];
    int kl = blockIdx.x, tid = threadIdx.x;
    for (int j = tid; j < 1024; j += 256) { Xxs[j] = g_Xx[kl*1024+j]; Xys[j] = g_Xy[kl*1024+j]; }
    for (int j = tid; j < 4096; j += 256) {
        int o = j >> 6, i = j & 63;
        Wxs[o*66+i] = g_Wtx[kl*4096+j];
        Wys[o*66+i] = g_Wty[kl*4096+j];
    }
    __syncthreads();
    int b = tid >> 4, o0 = tid & 15;
    u64 aA[4], aB[4], aC[4], aD[4];
    #pragma unroll
    for (int j = 0; j < 4; j++) { aA[j]=aB[j]=aC[j]=aD[j]=0ull; }
    #pragma unroll 4
    for (int ip = 0; ip < 32; ip++) {
        u64 Xxp = *(u64*)(Xxs + b*64 + 2*ip);
        u64 Xyp = *(u64*)(Xys + b*64 + 2*ip);
        #pragma unroll
        for (int j = 0; j < 4; j++) {
            int o = o0 + 16*j;
            u64 Wxp = *(u64*)(Wxs + o*66 + 2*ip);
            u64 Wyp = *(u64*)(Wys + o*66 + 2*ip);
            fma2(aA[j], Xxp, Wxp); fma2(aB[j], Xyp, Wyp);
            fma2(aC[j], Xxp, Wyp); fma2(aD[j], Xyp, Wxp);
        }
    }
    #pragma unroll
    for (int j = 0; j < 4; j++) {
        int bo = b*64 + o0 + 16*j;
        g_OFx[bo*256 + kl] = hadd(aA[j]) - hadd(aB[j]);
        g_OFy[bo*256 + kl] = hadd(aC[j]) + hadd(aD[j]);
    }
}

// inverse along h per (b,o): A[h][l] = sc * sum_k F[k,l] e^{+i k h th}
__global__ void __launch_bounds__(256) k_invA() {
    __shared__ u64 tcT[128*9], tsT[128*9];
    __shared__ float Fxs[16*18], Fys[16*18];
    int tid = threadIdx.x, bo = blockIdx.x;
    for (int e = tid; e < 1024; e += 256) {
        int h = e >> 3, kp = e & 7;
        float s0, c0, s1, c1;
        sincospif((float)(h * (2*kp))   * (1.f/64.f), &s0, &c0);
        sincospif((float)(h * (2*kp+1)) * (1.f/64.f), &s1, &c1);
        tcT[h*9+kp] = pk2(c0, c1);
        tsT[h*9+kp] = pk2(-s0, -s1);
    }
    {
        int k = tid >> 4, l = tid & 15;
        Fxs[l*18+k] = g_OFx[bo*256 + tid];
        Fys[l*18+k] = g_OFy[bo*256 + tid];
    }
    __syncthreads();
    int h = tid >> 1, l0 = (tid & 1) * 8;
    u64 aA[8], aB[8], aC[8], aD[8];
    #pragma unroll
    for (int j = 0; j < 8; j++) { aA[j]=aB[j]=aC[j]=aD[j]=0ull; }
    #pragma unroll
    for (int kp = 0; kp < 8; kp++) {
        u64 tck = tcT[h*9+kp], tsk = tsT[h*9+kp];
        #pragma unroll
        for (int j = 0; j < 8; j++) {
            u64 Fxp = *(u64*)(Fxs + (l0+j)*18 + 2*kp);
            u64 Fyp = *(u64*)(Fys + (l0+j)*18 + 2*kp);
            fma2(aA[j], tck, Fxp); fma2(aB[j], tsk, Fyp);
            fma2(aC[j], tck, Fyp); fma2(aD[j], tsk, Fxp);
        }
    }
    int b = bo >> 6, o = bo & 63;
    float* ox = g_Ax + ((size_t)(b*128 + h)*64 + o)*16 + l0;
    float* oy = g_Ay + ((size_t)(b*128 + h)*64 + o)*16 + l0;
    float rx[8], ry[8];
    #pragma unroll
    for (int j = 0; j < 8; j++) {
        float sc = (l0 + j == 0) ? 0.0078125f : 0.015625f;
        rx[j] = (hadd(aA[j]) + hadd(aB[j])) * sc;
        ry[j] = (hadd(aC[j]) - hadd(aD[j])) * sc;
    }
    *(float4*)(ox)   = make_float4(rx[0],rx[1],rx[2],rx[3]);
    *(float4*)(ox+4) = make_float4(rx[4],rx[5],rx[6],rx[7]);
    *(float4*)(oy)   = make_float4(ry[0],ry[1],ry[2],ry[3]);
    *(float4*)(oy+4) = make_float4(ry[4],ry[5],ry[6],ry[7]);
}

// final fused per (b,h): irfft E/O fold + bypass GEMM + GeLU + temb
__global__ void __launch_bounds__(256, 3) k_final(const float* __restrict__ x,
                                                  const float* __restrict__ bypb,
                                                  float* __restrict__ out) {
    extern __shared__ char sm[];
    float* xs  = (float*)sm;            // 64 x 132            33792 B
    float* bw  = (float*)(sm + 33792);  // [i][o]              16384 B
    float* Axs = (float*)(sm + 50176);  //                      4096 B
    float* Ays = (float*)(sm + 54272);  //                      4096 B
    u64*   tcw = (u64*)(sm + 58368);    // [l][wp<32] s34       4352 B
    u64*   tsw = (u64*)(sm + 62720);    //                      4352 B
    float* pb  = (float*)(sm + 67072);
    float* pj  = (float*)(sm + 67328);  // -> 67584

    int tid = threadIdx.x;
    int b = blockIdx.x >> 7, h = blockIdx.x & 127;
    const float* xbase = x + (size_t)b * 64 * 16384 + h * 128;

    #pragma unroll
    for (int j = 0; j < 8; j++) {
        int idx4 = tid + j * 256;
        int i = idx4 >> 5, wq = idx4 & 31;
        *(float4*)(xs + i*132 + wq*4) = *(const float4*)(xbase + i*16384 + wq*4);
    }
    #pragma unroll
    for (int j = 0; j < 4; j++)
        ((float4*)bw)[tid + j*256] = ((const float4*)g_bwT)[tid + j*256];
    {
        const float* Abx = g_Ax + (size_t)(b*128 + h) * 1024;
        const float* Aby = g_Ay + (size_t)(b*128 + h) * 1024;
        *(float4*)(Axs + tid*4) = *(const float4*)(Abx + tid*4);
        *(float4*)(Ays + tid*4) = *(const float4*)(Aby + tid*4);
    }
    for (int e = tid; e < 512; e += 256) {
        int l = e >> 5, wp = e & 31;
        float s0, c0, s1, c1;
        sincospif((float)(l * (2*wp))   * (1.f/64.f), &s0, &c0);
        sincospif((float)(l * (2*wp+1)) * (1.f/64.f), &s1, &c1);
        tcw[l*34+wp] = pk2(c0, c1);
        tsw[l*34+wp] = pk2(-s0, -s1);
    }
    if (tid < 64) { pb[tid] = bypb[tid]; pj[tid] = g_proj[b*64 + tid]; }
    __syncthreads();

    int o0 = (tid >> 4) * 4, wL = tid & 15;
    int wA = wL * 4, wB = 64 + wL * 4;

    u64 acc[4][4];
    {
        u64 E[4][2], O[4][2];
        #pragma unroll
        for (int j = 0; j < 4; j++) { E[j][0]=E[j][1]=O[j][0]=O[j][1]=0ull; }
        #pragma unroll 4
        for (int l = 0; l < 16; l++) {
            ulonglong2 cA = *(ulonglong2*)(tcw + l*34 + 2*wL);
            ulonglong2 sA = *(ulonglong2*)(tsw + l*34 + 2*wL);
            #pragma unroll
            for (int j = 0; j < 4; j++) {
                u64 ax = pk2(Axs[(o0+j)*16 + l], Axs[(o0+j)*16 + l]);
                u64 ay = pk2(Ays[(o0+j)*16 + l], Ays[(o0+j)*16 + l]);
                if ((l & 1) == 0) {
                    fma2(E[j][0], ax, cA.x); fma2(E[j][0], ay, sA.x);
                    fma2(E[j][1], ax, cA.y); fma2(E[j][1], ay, sA.y);
                } else {
                    fma2(O[j][0], ax, cA.x); fma2(O[j][0], ay, sA.x);
                    fma2(O[j][1], ax, cA.y); fma2(O[j][1], ay, sA.y);
                }
            }
        }
        #pragma unroll
        for (int j = 0; j < 4; j++) {
            acc[j][0] = add2(E[j][0], O[j][0]);
            acc[j][1] = add2(E[j][1], O[j][1]);
            acc[j][2] = sub2(E[j][0], O[j][0]);
            acc[j][3] = sub2(E[j][1], O[j][1]);
        }
    }

    #pragma unroll 4
    for (int i = 0; i < 64; i++) {
        ulonglong2 xa = *(ulonglong2*)(xs + i*132 + wA);
        ulonglong2 xc = *(ulonglong2*)(xs + i*132 + wB);
        float2 b01f = *(float2*)(bw + i*64 + o0);
        float2 b23f = *(float2*)(bw + i*64 + o0 + 2);
        u64 b0 = pk2(b01f.x, b01f.x), b1 = pk2(b01f.y, b01f.y);
        u64 b2 = pk2(b23f.x, b23f.x), b3 = pk2(b23f.y, b23f.y);
        fma2(acc[0][0], b0, xa.x); fma2(acc[0][1], b0, xa.y);
        fma2(acc[0][2], b0, xc.x); fma2(acc[0][3], b0, xc.y);
        fma2(acc[1][0], b1, xa.x); fma2(acc[1][1], b1, xa.y);
        fma2(acc[1][2], b1, xc.x); fma2(acc[1][3], b1, xc.y);
        fma2(acc[2][0], b2, xa.x); fma2(acc[2][1], b2, xa.y);
        fma2(acc[2][2], b2, xc.x); fma2(acc[2][3], b2, xc.y);
        fma2(acc[3][0], b3, xa.x); fma2(acc[3][1], b3, xa.y);
        fma2(acc[3][2], b3, xc.x); fma2(acc[3][3], b3, xc.y);
    }

    float* obase = out + (size_t)b * 64 * 16384 + h * 128;
    const float is2 = 0.70710678118654752f;
    #pragma unroll
    for (int j = 0; j < 4; j++) {
        int o = o0 + j;
        float bias = pb[o], pr = pj[o];
        float g[8];
        #pragma unroll
        for (int p = 0; p < 4; p++) {
            float2 t = up2(acc[j][p]);
            float v0 = t.x + bias, v1 = t.y + bias;
            g[2*p]   = 0.5f * v0 * (1.f + erff(v0 * is2)) + pr;
            g[2*p+1] = 0.5f * v1 * (1.f + erff(v1 * is2)) + pr;
        }
        *(float4*)(obase + o*16384 + wA) = make_float4(g[0],g[1],g[2],g[3]);
        *(float4*)(obase + o*16384 + wB) = make_float4(g[4],g[5],g[6],g[7]);
    }
}

extern "C" void kernel_launch(void* const* d_in, const int* in_sizes, int n_in,
                              void* d_out, int out_size) {
    const float* x     = (const float*)d_in[0];
    const float* t_emb = (const float*)d_in[1];
    const float* wr    = (const float*)d_in[2];
    const float* wi    = (const float*)d_in[3];
    const float* bypw  = (const float*)d_in[4];
    const float* bypb  = (const float*)d_in[5];
    const float* tw    = (const float*)d_in[6];
    const float* tb    = (const float*)d_in[7];
    float* out = (float*)d_out;

    cudaFuncSetAttribute(k_fwd,   cudaFuncAttributeMaxDynamicSharedMemorySize, 100864);
    cudaFuncSetAttribute(k_final, cudaFuncAttributeMaxDynamicSharedMemorySize, 67584);

    k_proj<<<1024, 128>>>(t_emb, tw, tb);
    k_wt  <<<dim3(8, 128), dim3(32, 8)>>>(wr, wi);
    k_bwt <<<16, 256>>>(bypw);
    k_fwd <<<1024, 256, 100864>>>(x);
    k_spec<<<256, 256>>>();
    k_invA<<<1024, 256>>>();
    k_final<<<2048, 256, 67584>>>(x, bypb, out);
}